// round 13
// baseline (speedup 1.0000x reference)
#include <cuda_runtime.h>
#include <cuda_bf16.h>
#include <cstdint>

#define B 384
#define D 128
#define TS 32                   // Gram tile size
#define GT (B / TS)             // 12 tiles per dim
#define NBLK1 (GT * GT)         // 144 gram blocks (single wave)
#define THR1 256
#define PITCH4 33               // float4 pitch (+1 pad) -> conflict-free
#define NA 3
#define NB (B / NA)             // 128 triplet blocks
#define THR2 384
#define NWARP2 (THR2 / 32)      // 12
#define MARGIN 0.5f

__device__ float g_G[B * B];          // Gram matrix scratch
__device__ float g_nrm[B];            // squared norms (coalesced for consumer)
__device__ float g_psum[NB];
__device__ float g_pcnt[NB];
__device__ unsigned int g_ticket;     // zero-init; reset by last block

__device__ __forceinline__ void cp_async16(uint32_t dst, const void* src) {
    asm volatile("cp.async.cg.shared.global [%0], [%1], 16;" :: "r"(dst), "l"(src));
}

// ======================= Kernel 1: G = E * E^T (tiled) =======================
__global__ __launch_bounds__(THR1) void gram_kernel(const float* __restrict__ emb)
{
    __shared__ float4 sA[TS * PITCH4];
    __shared__ float4 sB[TS * PITCH4];

    const int tid = threadIdx.x;
    const int ty  = blockIdx.x / GT;
    const int tx  = blockIdx.x % GT;

    const float4* g4 = (const float4*)emb;         // B x 32 float4
    const uint32_t sA_u = (uint32_t)__cvta_generic_to_shared(sA);
    const uint32_t sB_u = (uint32_t)__cvta_generic_to_shared(sB);

    #pragma unroll
    for (int it = 0; it < (TS * (D / 4)) / THR1; it++) {    // 4 iters
        int g = tid + THR1 * it;                    // 0..1023
        int r = g >> 5, c = g & 31;
        uint32_t soff = (uint32_t)((r * PITCH4 + c) * 16);
        cp_async16(sA_u + soff, g4 + (ty * TS + r) * (D / 4) + c);
        cp_async16(sB_u + soff, g4 + (tx * TS + r) * (D / 4) + c);
    }
    asm volatile("cp.async.commit_group;" ::: "memory");
    asm volatile("cp.async.wait_group 0;" ::: "memory");
    __syncthreads();

    // diagonal blocks also emit norms (deterministic shfl tree, coalesced STG)
    if (ty == tx) {
        const int r = tid >> 3;        // 0..31
        const int q = tid & 7;         // 8-lane groups
        const float4* row = sA + r * PITCH4;
        float pp = 0.f;
        #pragma unroll
        for (int c = 0; c < 4; c++) {
            float4 x = row[q * 4 + c];
            pp = fmaf(x.x, x.x, fmaf(x.y, x.y, fmaf(x.z, x.z, fmaf(x.w, x.w, pp))));
        }
        pp += __shfl_down_sync(0xFFFFFFFFu, pp, 4, 8);
        pp += __shfl_down_sync(0xFFFFFFFFu, pp, 2, 8);
        pp += __shfl_down_sync(0xFFFFFFFFu, pp, 1, 8);
        if (q == 0) g_nrm[ty * TS + r] = pp;
    }

    // 32x32 output tile: thread -> row i, 4 cols at jg*4
    const int i  = tid & 31;
    const int jg = tid >> 5;
    float a0 = 0.f, a1 = 0.f, a2 = 0.f, a3 = 0.f;
    const float4* arow = sA + i * PITCH4;
    const float4* b0 = sB + (jg * 4 + 0) * PITCH4;
    const float4* b1 = sB + (jg * 4 + 1) * PITCH4;
    const float4* b2 = sB + (jg * 4 + 2) * PITCH4;
    const float4* b3 = sB + (jg * 4 + 3) * PITCH4;

    #pragma unroll 8
    for (int k = 0; k < D / 4; k++) {
        float4 x = arow[k];
        float4 p = b0[k];   // warp-uniform -> broadcast
        a0 = fmaf(x.x, p.x, fmaf(x.y, p.y, fmaf(x.z, p.z, fmaf(x.w, p.w, a0))));
        p = b1[k];
        a1 = fmaf(x.x, p.x, fmaf(x.y, p.y, fmaf(x.z, p.z, fmaf(x.w, p.w, a1))));
        p = b2[k];
        a2 = fmaf(x.x, p.x, fmaf(x.y, p.y, fmaf(x.z, p.z, fmaf(x.w, p.w, a2))));
        p = b3[k];
        a3 = fmaf(x.x, p.x, fmaf(x.y, p.y, fmaf(x.z, p.z, fmaf(x.w, p.w, a3))));
    }

    *(float4*)&g_G[(ty * TS + i) * B + tx * TS + jg * 4] = make_float4(a0, a1, a2, a3);

    // release the dependent (PDL) launch as early as possible
    cudaTriggerProgrammaticLaunchCompletion();
}

// ================= Kernel 2: triplet reduction from G (PDL consumer) =========
__global__ __launch_bounds__(THR2) void triplet_kernel(
    const int* __restrict__ labels,
    float* __restrict__ out)
{
    __shared__ float snrm[B];
    __shared__ int   slab[B];
    __shared__ float dpos[NA][B];
    __shared__ int   npos[NA];
    __shared__ float rsum[NWARP2];
    __shared__ float rcnt[NWARP2];
    __shared__ int   is_last;

    const int t  = threadIdx.x;      // == column j
    const int ab = blockIdx.x * NA;

    // ---- G-independent prologue (overlaps with gram kernel) ----
    slab[t] = labels[t];
    if (t < NA) npos[t] = 0;

    // ---- wait for gram kernel completion (memory-visible) ----
    cudaGridDependencySynchronize();

    snrm[t] = __ldcg(&g_nrm[t]);             // coalesced 1.5KB read
    __syncthreads();

    const int lt = slab[t];
    float dist[NA];
    #pragma unroll
    for (int aa = 0; aa < NA; aa++) {
        const int a = ab + aa;
        float Gaj = __ldcg(&g_G[a * B + t]);          // coalesced row read
        dist[aa] = fmaxf(snrm[a] - 2.f * Gaj + snrm[t], 0.f);
        if (lt == slab[a] && t != a) {
            int idx = atomicAdd(&npos[aa], 1);
            dpos[aa][idx] = dist[aa];
        }
    }
    __syncthreads();

    float sum = 0.f, cnt = 0.f;
    #pragma unroll
    for (int aa = 0; aa < NA; aa++) {
        if (lt != slab[ab + aa]) {
            const float dn = dist[aa];
            const int np = npos[aa];
            for (int p = 0; p < np; p++) {
                float v = dpos[aa][p] - dn + MARGIN;
                if (v > 1e-16f) { sum += v; cnt += 1.f; }
            }
        }
    }

    // block reduction (12 warps)
    const int lane = t & 31;
    const int warp = t >> 5;
    #pragma unroll
    for (int off = 16; off > 0; off >>= 1) {
        sum += __shfl_down_sync(0xFFFFFFFFu, sum, off);
        cnt += __shfl_down_sync(0xFFFFFFFFu, cnt, off);
    }
    if (lane == 0) { rsum[warp] = sum; rcnt[warp] = cnt; }
    __syncthreads();
    if (warp == 0) {
        float s = (lane < NWARP2) ? rsum[lane] : 0.f;
        float c = (lane < NWARP2) ? rcnt[lane] : 0.f;
        #pragma unroll
        for (int off = 16; off > 0; off >>= 1) {
            s += __shfl_down_sync(0xFFFFFFFFu, s, off);
            c += __shfl_down_sync(0xFFFFFFFFu, c, off);
        }
        if (lane == 0) {
            g_psum[blockIdx.x] = s;
            g_pcnt[blockIdx.x] = c;
        }
    }

    // last-block final reduction
    __threadfence();
    if (t == 0) {
        unsigned int tk = atomicAdd(&g_ticket, 1u);
        is_last = (tk == NB - 1);
    }
    __syncthreads();

    if (is_last && warp == 0) {
        __threadfence();
        volatile float* vs = g_psum;
        volatile float* vc = g_pcnt;
        double s = 0.0, c = 0.0;
        #pragma unroll
        for (int i = lane; i < NB; i += 32) {
            s += (double)vs[i];
            c += (double)vc[i];
        }
        #pragma unroll
        for (int off = 16; off > 0; off >>= 1) {
            s += __shfl_down_sync(0xFFFFFFFFu, s, off);
            c += __shfl_down_sync(0xFFFFFFFFu, c, off);
        }
        if (lane == 0) {
            out[0] = (float)(s / (c + 1e-16));
            g_ticket = 0;                  // reset for graph replay
        }
    }
}

extern "C" void kernel_launch(void* const* d_in, const int* in_sizes, int n_in,
                              void* d_out, int out_size) {
    const float* emb    = (const float*)d_in[0];
    const int*   labels = (const int*)d_in[1];
    float*       out    = (float*)d_out;

    gram_kernel<<<NBLK1, THR1>>>(emb);

    // PDL: triplet_kernel launches while gram_kernel runs; it self-synchronizes
    // via cudaGridDependencySynchronize() before touching g_G / g_nrm.
    cudaLaunchConfig_t cfg = {};
    cfg.gridDim  = dim3(NB, 1, 1);
    cfg.blockDim = dim3(THR2, 1, 1);
    cfg.dynamicSmemBytes = 0;
    cfg.stream = 0;   // legacy default stream (the one the harness captures)
    cudaLaunchAttribute attrs[1];
    attrs[0].id = cudaLaunchAttributeProgrammaticStreamSerialization;
    attrs[0].val.programmaticStreamSerializationAllowed = 1;
    cfg.attrs = attrs;
    cfg.numAttrs = 1;
    cudaLaunchKernelEx(&cfg, triplet_kernel, labels, out);
}